// round 2
// baseline (speedup 1.0000x reference)
#include <cuda_runtime.h>

#define NROWS 16384
#define DCOLS 2048
#define TPB   256

// Scratch (device globals — no allocations allowed).
__device__ float        g_row_cos[NROWS];
__device__ unsigned int g_counter = 0;   // self-resetting: last block zeroes it

// One block (256 threads) per row; the last block to finish also does the
// final mean-reduce (threadfence-reduction pattern).
__global__ void __launch_bounds__(TPB) cosine_loss_fused(
    const float* __restrict__ cxr, const float* __restrict__ ehr,
    float* __restrict__ out)
{
    const int row = blockIdx.x;
    const float4* __restrict__ a = reinterpret_cast<const float4*>(ehr + (size_t)row * DCOLS);
    const float4* __restrict__ b = reinterpret_cast<const float4*>(cxr + (size_t)row * DCOLS);
    const int t = threadIdx.x;

    // 2048 floats = 512 float4 per tensor; 256 threads -> 2 float4 each.
    // All 4 loads front-batched for MLP.
    float4 a0 = a[t];
    float4 b0 = b[t];
    float4 a1 = a[t + TPB];
    float4 b1 = b[t + TPB];

    float dot, na, nb;
    dot  = a0.x*b0.x + a0.y*b0.y + a0.z*b0.z + a0.w*b0.w;
    na   = a0.x*a0.x + a0.y*a0.y + a0.z*a0.z + a0.w*a0.w;
    nb   = b0.x*b0.x + b0.y*b0.y + b0.z*b0.z + b0.w*b0.w;
    dot += a1.x*b1.x + a1.y*b1.y + a1.z*b1.z + a1.w*b1.w;
    na  += a1.x*a1.x + a1.y*a1.y + a1.z*a1.z + a1.w*a1.w;
    nb  += b1.x*b1.x + b1.y*b1.y + b1.z*b1.z + b1.w*b1.w;

    #pragma unroll
    for (int o = 16; o > 0; o >>= 1) {
        dot += __shfl_xor_sync(0xffffffffu, dot, o);
        na  += __shfl_xor_sync(0xffffffffu, na,  o);
        nb  += __shfl_xor_sync(0xffffffffu, nb,  o);
    }

    __shared__ float sdot[8], sna[8], snb[8];
    __shared__ bool  s_is_last;
    const int w = t >> 5, l = t & 31;
    if (l == 0) { sdot[w] = dot; sna[w] = na; snb[w] = nb; }
    __syncthreads();

    if (t == 0) {
        float d = 0.f, x = 0.f, y = 0.f;
        #pragma unroll
        for (int i = 0; i < 8; i++) { d += sdot[i]; x += sna[i]; y += snb[i]; }
        g_row_cos[row] = d * rsqrtf(x * y);
        __threadfence();                                  // publish before arrive
        unsigned int old = atomicAdd(&g_counter, 1u);
        s_is_last = (old == (unsigned)(NROWS - 1));
    }
    __syncthreads();

    if (!s_is_last) return;

    // ── Last block: deterministic final reduce of all 16384 cosines ──
    __threadfence();   // order counter-read before g_row_cos reads
    const float4* rc = reinterpret_cast<const float4*>(g_row_cos);
    float s = 0.f;
    // 16384 floats = 4096 float4; 256 threads -> 16 each. Bypass L1 (__ldcg):
    // other CTAs' STG results live in L2, our L1 could be stale.
    #pragma unroll
    for (int i = 0; i < 16; i++) {
        float4 v = __ldcg(&rc[t + i * TPB]);
        s += v.x + v.y + v.z + v.w;
    }

    #pragma unroll
    for (int o = 16; o > 0; o >>= 1)
        s += __shfl_xor_sync(0xffffffffu, s, o);

    if (l == 0) sdot[w] = s;   // reuse smem
    __syncthreads();

    if (t == 0) {
        float tot = 0.f;
        #pragma unroll
        for (int i = 0; i < 8; i++) tot += sdot[i];
        out[0] = 1.0f - tot / (float)NROWS;
        g_counter = 0;          // reset for next graph replay
    }
}

extern "C" void kernel_launch(void* const* d_in, const int* in_sizes, int n_in,
                              void* d_out, int out_size)
{
    const float* cxr = (const float*)d_in[0];
    const float* ehr = (const float*)d_in[1];
    float* out = (float*)d_out;
    cosine_loss_fused<<<NROWS, TPB>>>(cxr, ehr, out);
}